// round 4
// baseline (speedup 1.0000x reference)
#include <cuda_runtime.h>

#define DET       736
#define TPR       46          // threads per row (736 = 16*46)
#define THREADS   92          // 2 rows per block
#define PITCH     139         // u64 (float-pair) entries per plane
#define ROWSTRIDE 1118        // 8*PITCH=1112, padded so ROWSTRIDE ≡ 14 (mod 16)
#define NPAIR     1112        // staged pairs per row
#define NODD      736
#define NTAPPAD   768
#define RAWF      (2*DET)     // floats per row-pair tile
#define CHUNKS16  368         // 16B chunks per tile (5888B)
#define NBLK      888         // persistent grid: 148 SMs * 6 blocks

typedef unsigned long long u64;

__device__ u64   g_fz2[NTAPPAD];  // splatted odd taps (filt[2j], filt[2j]); zero-padded
__device__ float g_fc;            // center tap filt[735]

__device__ __forceinline__ u64 pk2(float a, float b) {
    u64 r; asm("mov.b64 %0, {%1, %2};" : "=l"(r) : "f"(a), "f"(b)); return r;
}
__device__ __forceinline__ void fma2(u64 &acc, u64 a, u64 b) {
    asm("fma.rn.f32x2 %0, %1, %2, %0;" : "+l"(acc) : "l"(a), "l"(b));
}
__device__ __forceinline__ void cpa16(unsigned s, const void* g) {
    asm volatile("cp.async.ca.shared.global [%0], [%1], 16;" :: "r"(s), "l"(g));
}
__device__ __forceinline__ void cpa_commit() {
    asm volatile("cp.async.commit_group;");
}
__device__ __forceinline__ void cpa_wait0() {
    asm volatile("cp.async.wait_group 0;");
}

__global__ void prep_kernel(const float* __restrict__ filt) {
    int j = threadIdx.x;
    if (j < NODD) {
        float f = filt[2 * j];
        g_fz2[j] = pk2(f, f);
    } else if (j < NTAPPAD) {
        g_fz2[j] = 0ull;
    }
    if (j == 0) g_fc = filt[735];
}

template <int S>
__device__ __forceinline__ void tapstep(u64 ff, u64* acc, const u64* w) {
#pragma unroll
    for (int q = 0; q < 8; ++q) fma2(acc[q], ff, w[(S + q) & 15]);
}

__global__ void __launch_bounds__(THREADS)
conv_kernel(const float* __restrict__ x, float* __restrict__ out,
            const int* __restrict__ scale_p, int nrows, int ntiles) {
    __shared__ u64 xs2[2 * ROWSTRIDE];                 // pair-plane weighted data
    __shared__ __align__(16) float raw[2][RAWF];       // cp.async staging (double buf)
    __shared__ float cwS[DET];                         // cosine weights

    const int tid = threadIdx.x;

    int s_i = *scale_p;
    float scale = (s_i >= 1 && s_i <= 1024) ? (float)s_i : __int_as_float(s_i);
    const float kk = scale * 1.0e-3f;

    // per-block constants
    for (int i = tid; i < DET; i += THREADS)
        cwS[i] = 0.05f * __cosf(((float)i - 367.5f) * kk);

    const int row = tid / TPR;            // 0 or 1
    const int tl  = tid - row * TPR;      // thread-in-row
    const u64* wbase = &xs2[row * ROWSTRIDE + tl];
    const float fc = g_fc;

    unsigned rawS0 = (unsigned)__cvta_generic_to_shared(&raw[0][0]);
    unsigned rawS1 = (unsigned)__cvta_generic_to_shared(&raw[1][0]);

    // ---- prologue: prefetch first tile into buf 0 ----
    int t0 = blockIdx.x;
    if (t0 < ntiles) {
        const char* g = (const char*)x + (size_t)t0 * RAWF * 4;
        int valid = (nrows - 2 * t0 >= 2) ? CHUNKS16 : CHUNKS16 / 2;
        for (int c = tid; c < CHUNKS16; c += THREADS) {
            if (c < valid) cpa16(rawS0 + c * 16, g + (size_t)c * 16);
            else *(float4*)&raw[0][c * 4] = make_float4(0.f, 0.f, 0.f, 0.f);
        }
    }
    cpa_commit();

    int buf = 0;
    for (int t = t0; t < ntiles; t += gridDim.x) {
        cpa_wait0();
        __syncthreads();                      // raw[buf] visible; xs2 reusable

        // ---- transform: raw[buf] -> weighted, pair-plane xs2 ----
        const float* rb = raw[buf];
        for (int e = tid; e < NPAIR; e += THREADS) {
            int base = ((e & 7) * PITCH) + (e >> 3);
            int p0 = 2 * e - 737;
            int p1 = p0 + 1;
            bool v0 = (p0 >= 0) & (p0 < DET);
            bool v1 = (p1 >= 0) & (p1 < DET);
            float a0 = v0 ? rb[p0] * cwS[p0] : 0.0f;
            float a1 = v1 ? rb[p1] * cwS[p1] : 0.0f;
            xs2[base] = pk2(a0, a1);
            float b0 = v0 ? rb[DET + p0] * cwS[p0] : 0.0f;
            float b1 = v1 ? rb[DET + p1] * cwS[p1] : 0.0f;
            xs2[ROWSTRIDE + base] = pk2(b0, b1);
        }
        __syncthreads();                      // xs2 ready; raw[buf] consumed

        // ---- prefetch next tile into raw[buf^1] (overlaps compute) ----
        int tn = t + gridDim.x;
        if (tn < ntiles) {
            const char* g = (const char*)x + (size_t)tn * RAWF * 4;
            int valid = (nrows - 2 * tn >= 2) ? CHUNKS16 : CHUNKS16 / 2;
            unsigned rS = buf ? rawS0 : rawS1;
            float* rd = buf ? raw[0] : raw[1];
            for (int c = tid; c < CHUNKS16; c += THREADS) {
                if (c < valid) cpa16(rS + c * 16, g + (size_t)c * 16);
                else *(float4*)&rd[c * 4] = make_float4(0.f, 0.f, 0.f, 0.f);
            }
        }
        cpa_commit();

        // ---- compute (identical to round-3 inner loop) ----
        u64 acc[8];
#pragma unroll
        for (int q = 0; q < 8; ++q) {
            int h0 = 368 + q, h1 = 369 + q;
            float a = fc * ((const float*)&wbase[(h0 & 7) * PITCH + (h0 >> 3)])[1];
            float b = fc * ((const float*)&wbase[(h1 & 7) * PITCH + (h1 >> 3)])[0];
            acc[q] = pk2(a, b);
        }

        u64 w[16];
#pragma unroll
        for (int i = 0; i < 15; ++i) {
            int h = 1 + i;
            w[i] = wbase[(h & 7) * PITCH + (h >> 3)];
        }
        w[15] = 0ull;

        u64 fa[8], fb[8];
#pragma unroll
        for (int q = 0; q < 8; ++q) {
            fa[q] = __ldg(&g_fz2[q]);
            fb[q] = __ldg(&g_fz2[8 + q]);
        }

        const u64* wk  = wbase;
        const u64* fpt = g_fz2;

#pragma unroll 1
        for (int m = 0; m < NODD / 16; ++m) {
            tapstep<0>(fa[0], acc, w);  w[15] = wk[0 * PITCH + 2];  fa[0] = __ldg(fpt + 16);
            tapstep<1>(fa[1], acc, w);  w[0]  = wk[1 * PITCH + 2];  fa[1] = __ldg(fpt + 17);
            tapstep<2>(fa[2], acc, w);  w[1]  = wk[2 * PITCH + 2];  fa[2] = __ldg(fpt + 18);
            tapstep<3>(fa[3], acc, w);  w[2]  = wk[3 * PITCH + 2];  fa[3] = __ldg(fpt + 19);
            tapstep<4>(fa[4], acc, w);  w[3]  = wk[4 * PITCH + 2];  fa[4] = __ldg(fpt + 20);
            tapstep<5>(fa[5], acc, w);  w[4]  = wk[5 * PITCH + 2];  fa[5] = __ldg(fpt + 21);
            tapstep<6>(fa[6], acc, w);  w[5]  = wk[6 * PITCH + 2];  fa[6] = __ldg(fpt + 22);
            tapstep<7>(fa[7], acc, w);  w[6]  = wk[7 * PITCH + 2];  fa[7] = __ldg(fpt + 23);
            tapstep<8> (fb[0], acc, w); w[7]  = wk[0 * PITCH + 3];  fb[0] = __ldg(fpt + 24);
            tapstep<9> (fb[1], acc, w); w[8]  = wk[1 * PITCH + 3];  fb[1] = __ldg(fpt + 25);
            tapstep<10>(fb[2], acc, w); w[9]  = wk[2 * PITCH + 3];  fb[2] = __ldg(fpt + 26);
            tapstep<11>(fb[3], acc, w); w[10] = wk[3 * PITCH + 3];  fb[3] = __ldg(fpt + 27);
            tapstep<12>(fb[4], acc, w); w[11] = wk[4 * PITCH + 3];  fb[4] = __ldg(fpt + 28);
            tapstep<13>(fb[5], acc, w); w[12] = wk[5 * PITCH + 3];  fb[5] = __ldg(fpt + 29);
            tapstep<14>(fb[6], acc, w); w[13] = wk[6 * PITCH + 3];  fb[6] = __ldg(fpt + 30);
            tapstep<15>(fb[7], acc, w); w[14] = wk[7 * PITCH + 3];  fb[7] = __ldg(fpt + 31);
            wk  += 2;
            fpt += 16;
        }

        int row_g = 2 * t + row;
        if (row_g < nrows) {
            u64* orow = (u64*)(out + (size_t)row_g * DET);
#pragma unroll
            for (int q = 0; q < 8; ++q) orow[8 * tl + q] = acc[q];
        }

        buf ^= 1;
    }
}

extern "C" void kernel_launch(void* const* d_in, const int* in_sizes, int n_in,
                              void* d_out, int out_size) {
    const float* sino  = (const float*)d_in[0];
    const float* filt  = (const float*)d_in[1];
    const int*   scale = (const int*)d_in[2];
    float* out = (float*)d_out;

    int nrows  = in_sizes[0] / DET;          // 18432
    int ntiles = (nrows + 1) / 2;            // 9216 row-pairs
    int nblk   = ntiles < NBLK ? ntiles : NBLK;

    prep_kernel<<<1, NTAPPAD>>>(filt);
    conv_kernel<<<nblk, THREADS>>>(sino, out, scale, nrows, ntiles);
}

// round 5
// speedup vs baseline: 1.2507x; 1.2507x over previous
#include <cuda_runtime.h>

#define DET       736
#define TPR       46          // threads per row (736 = 16*46 outputs, TOUT=16)
#define ROWS      8           // rows per block
#define THREADS   368         // 8*46 = 12 warps -> 3 per SMSP (balanced)
#define PITCH     139         // u64 (float-pair) entries per plane
#define ROWSTRIDE 1118        // 8*PITCH=1112, padded so ROWSTRIDE ≡ 14 (mod 16)
#define NPAIR     1112        // staged pairs per row
#define NODD      736
#define NTAPPAD   768
#define SMEM_BYTES (ROWS * ROWSTRIDE * 8)

typedef unsigned long long u64;

__device__ u64   g_fz2[NTAPPAD];  // splatted odd taps (filt[2j], filt[2j]); zero-padded
__device__ float g_fc;            // center tap filt[735]
__device__ float g_cw[DET];       // cosine fan-beam weights

__device__ __forceinline__ u64 pk2(float a, float b) {
    u64 r; asm("mov.b64 %0, {%1, %2};" : "=l"(r) : "f"(a), "f"(b)); return r;
}
__device__ __forceinline__ void fma2(u64 &acc, u64 a, u64 b) {
    asm("fma.rn.f32x2 %0, %1, %2, %0;" : "+l"(acc) : "l"(a), "l"(b));
}

__global__ void prep_kernel(const float* __restrict__ filt,
                            const int*   __restrict__ scale_p) {
    int j = threadIdx.x;
    if (j < NODD) {
        float f = filt[2 * j];
        g_fz2[j] = pk2(f, f);
    } else if (j < NTAPPAD) {
        g_fz2[j] = 0ull;
    }
    if (j == 0) g_fc = filt[735];
    if (j < DET) {
        int s_i = *scale_p;
        float scale = (s_i >= 1 && s_i <= 1024) ? (float)s_i : __int_as_float(s_i);
        g_cw[j] = 0.05f * cosf(((float)j - 367.5f) * scale * 1.0e-3f);
    }
}

template <int S>
__device__ __forceinline__ void tapstep(u64 ff, u64* acc, const u64* w) {
#pragma unroll
    for (int q = 0; q < 8; ++q) fma2(acc[q], ff, w[(S + q) & 15]);
}

__global__ void __launch_bounds__(THREADS, 2)
conv_kernel(const float* __restrict__ x, float* __restrict__ out, int nrows) {
    // per-row pair-plane layout: pair e = (xs[2e], xs[2e+1]) at plane e&7, idx e>>3
    // xs[i] = x[i-737] * cw[i-737]  (zero outside)
    extern __shared__ u64 xs2[];   // ROWS * ROWSTRIDE

    const int tid = threadIdx.x;
    const int row = tid / TPR;            // 0..7
    const int tl  = tid - row * TPR;      // 0..45

    const int row_g = blockIdx.x * ROWS + row;
    const bool rok = row_g < nrows;
    const float* __restrict__ xr = x + (size_t)row_g * DET;
    u64* __restrict__ xrow = xs2 + row * ROWSTRIDE;

    // ---- stage this row-group's row (weighted, padded, pair-transposed) ----
    for (int e = tl; e < NPAIR; e += TPR) {
        int base = ((e & 7) * PITCH) + (e >> 3);
        int p0 = 2 * e - 737;
        int p1 = p0 + 1;
        bool v0 = rok & (p0 >= 0) & (p0 < DET);
        bool v1 = rok & (p1 >= 0) & (p1 < DET);
        float a0 = v0 ? xr[p0] * __ldg(&g_cw[p0]) : 0.0f;
        float a1 = v1 ? xr[p1] * __ldg(&g_cw[p1]) : 0.0f;
        xrow[base] = pk2(a0, a1);
    }
    __syncthreads();

    const u64* wbase = xrow + tl;
    const float fc = g_fc;

    // ---- init accumulators with center tap ----
    u64 acc[8];
#pragma unroll
    for (int q = 0; q < 8; ++q) {
        int h0 = 368 + q, h1 = 369 + q;
        float a = fc * ((const float*)&wbase[(h0 & 7) * PITCH + (h0 >> 3)])[1];
        float b = fc * ((const float*)&wbase[(h1 & 7) * PITCH + (h1 >> 3)])[0];
        acc[q] = pk2(a, b);
    }

    // ---- 16-slot rotating window ----
    u64 w[16];
#pragma unroll
    for (int i = 0; i < 15; ++i) {
        int h = 1 + i;
        w[i] = wbase[(h & 7) * PITCH + (h >> 3)];
    }
    w[15] = 0ull;

    // ---- register double-buffered splatted taps ----
    u64 fa[8], fb[8];
#pragma unroll
    for (int q = 0; q < 8; ++q) {
        fa[q] = __ldg(&g_fz2[q]);
        fb[q] = __ldg(&g_fz2[8 + q]);
    }

    const u64* wk  = wbase;
    const u64* fpt = g_fz2;

#pragma unroll 1
    for (int m = 0; m < NODD / 16; ++m) {
        tapstep<0>(fa[0], acc, w);  w[15] = wk[0 * PITCH + 2];  fa[0] = __ldg(fpt + 16);
        tapstep<1>(fa[1], acc, w);  w[0]  = wk[1 * PITCH + 2];  fa[1] = __ldg(fpt + 17);
        tapstep<2>(fa[2], acc, w);  w[1]  = wk[2 * PITCH + 2];  fa[2] = __ldg(fpt + 18);
        tapstep<3>(fa[3], acc, w);  w[2]  = wk[3 * PITCH + 2];  fa[3] = __ldg(fpt + 19);
        tapstep<4>(fa[4], acc, w);  w[3]  = wk[4 * PITCH + 2];  fa[4] = __ldg(fpt + 20);
        tapstep<5>(fa[5], acc, w);  w[4]  = wk[5 * PITCH + 2];  fa[5] = __ldg(fpt + 21);
        tapstep<6>(fa[6], acc, w);  w[5]  = wk[6 * PITCH + 2];  fa[6] = __ldg(fpt + 22);
        tapstep<7>(fa[7], acc, w);  w[6]  = wk[7 * PITCH + 2];  fa[7] = __ldg(fpt + 23);
        tapstep<8> (fb[0], acc, w); w[7]  = wk[0 * PITCH + 3];  fb[0] = __ldg(fpt + 24);
        tapstep<9> (fb[1], acc, w); w[8]  = wk[1 * PITCH + 3];  fb[1] = __ldg(fpt + 25);
        tapstep<10>(fb[2], acc, w); w[9]  = wk[2 * PITCH + 3];  fb[2] = __ldg(fpt + 26);
        tapstep<11>(fb[3], acc, w); w[10] = wk[3 * PITCH + 3];  fb[3] = __ldg(fpt + 27);
        tapstep<12>(fb[4], acc, w); w[11] = wk[4 * PITCH + 3];  fb[4] = __ldg(fpt + 28);
        tapstep<13>(fb[5], acc, w); w[12] = wk[5 * PITCH + 3];  fb[5] = __ldg(fpt + 29);
        tapstep<14>(fb[6], acc, w); w[13] = wk[6 * PITCH + 3];  fb[6] = __ldg(fpt + 30);
        tapstep<15>(fb[7], acc, w); w[14] = wk[7 * PITCH + 3];  fb[7] = __ldg(fpt + 31);
        wk  += 2;
        fpt += 16;
    }

    // ---- store 16 outputs as 8 packed u64 ----
    if (rok) {
        u64* orow = (u64*)(out + (size_t)row_g * DET);
#pragma unroll
        for (int q = 0; q < 8; ++q) orow[8 * tl + q] = acc[q];
    }
}

extern "C" void kernel_launch(void* const* d_in, const int* in_sizes, int n_in,
                              void* d_out, int out_size) {
    const float* sino  = (const float*)d_in[0];
    const float* filt  = (const float*)d_in[1];
    const int*   scale = (const int*)d_in[2];
    float* out = (float*)d_out;

    int nrows = in_sizes[0] / DET;              // 18432
    int nblk  = (nrows + ROWS - 1) / ROWS;      // 2304

    static int smem_set = 0;
    if (!smem_set) {
        cudaFuncSetAttribute(conv_kernel,
                             cudaFuncAttributeMaxDynamicSharedMemorySize,
                             SMEM_BYTES);
        smem_set = 1;
    }

    prep_kernel<<<1, NTAPPAD>>>(filt, scale);
    conv_kernel<<<nblk, THREADS, SMEM_BYTES>>>(sino, out, nrows);
}

// round 7
// speedup vs baseline: 2.6553x; 2.1230x over previous
#include <cuda_runtime.h>
#include <cuda_bf16.h>
#include <cstdint>

#define DET      736
#define NPADDED  768
#define KPAD     768
#define MAXROWS  18432
#define MT       128
#define NT       128
#define KCH      64
#define NKC      12                       // K chunks per plane (768/64)
#define NCHK     36                       // 3 planes * 12
#define TILEB    16384                    // 128 rows * 128 B
#define BUFSZ    (2 * TILEB)              // A + B per stage
#define SMEM_DYN (2 * BUFSZ)              // double buffered = 64 KB

typedef uint32_t u32;

__device__ __nv_bfloat16 g_Ahi[(size_t)MAXROWS * KPAD];
__device__ __nv_bfloat16 g_Alo[(size_t)MAXROWS * KPAD];
__device__ __nv_bfloat16 g_Bhi[(size_t)NPADDED * KPAD];  // [n][k] = hi(h[n-k+735])
__device__ __nv_bfloat16 g_Blo[(size_t)NPADDED * KPAD];

__device__ __forceinline__ void cpa16(u32 s, const void* g) {
    asm volatile("cp.async.cg.shared.global [%0], [%1], 16;" :: "r"(s), "l"(g));
}
__device__ __forceinline__ void ldm4(u32 a, u32& r0, u32& r1, u32& r2, u32& r3) {
    asm volatile("ldmatrix.sync.aligned.m8n8.x4.shared.b16 {%0,%1,%2,%3}, [%4];"
                 : "=r"(r0), "=r"(r1), "=r"(r2), "=r"(r3) : "r"(a));
}
__device__ __forceinline__ void mma16816(float* c, const u32* a, const u32* b) {
    asm volatile(
        "mma.sync.aligned.m16n8k16.row.col.f32.bf16.bf16.f32 "
        "{%0,%1,%2,%3}, {%4,%5,%6,%7}, {%8,%9}, {%0,%1,%2,%3};"
        : "+f"(c[0]), "+f"(c[1]), "+f"(c[2]), "+f"(c[3])
        : "r"(a[0]), "r"(a[1]), "r"(a[2]), "r"(a[3]), "r"(b[0]), "r"(b[1]));
}

// ----------------- prep kernels -----------------

__global__ void prep_B(const float* __restrict__ filt) {
    int n = blockIdx.x;               // 0..767
    int tid = threadIdx.x;            // 192
    size_t o = (size_t)n * KPAD;
#pragma unroll
    for (int i = 0; i < 4; ++i) {
        int k = tid + i * 192;        // 0..767
        float v = (n < DET && k < DET) ? filt[n + 735 - k] : 0.0f;
        __nv_bfloat16 h = __float2bfloat16(v);
        float rem = v - __bfloat162float(h);
        g_Bhi[o + k] = h;
        g_Blo[o + k] = __float2bfloat16(rem);
    }
}

__global__ void prep_A(const float* __restrict__ x, const int* __restrict__ scale_p,
                       int nrows) {
    int row = blockIdx.x;
    if (row >= nrows || row >= MAXROWS) return;
    int tid = threadIdx.x;            // 192
    int s_i = *scale_p;
    float scale = (s_i >= 1 && s_i <= 1024) ? (float)s_i : __int_as_float(s_i);
    const float kk = scale * 1.0e-3f;
    const float* xr = x + (size_t)row * DET;
    size_t o = (size_t)row * KPAD;
#pragma unroll
    for (int i = 0; i < 4; ++i) {
        int k = tid + i * 192;
        float v = 0.0f;
        if (k < DET) v = xr[k] * (0.05f * cosf(((float)k - 367.5f) * kk));
        __nv_bfloat16 h = __float2bfloat16(v);
        float rem = v - __bfloat162float(h);
        g_Ahi[o + k] = h;
        g_Alo[o + k] = __float2bfloat16(rem);
    }
}

// ----------------- GEMM kernel -----------------

__device__ __forceinline__ void stage_chunk(int c, u32 sbuf, int m0, int n0, int tid) {
    int p  = c / NKC;
    int kc = c - p * NKC;
    int k0 = kc * KCH;
    const __nv_bfloat16* Asrc = (p < 2) ? g_Ahi : g_Alo;
    const __nv_bfloat16* Bsrc = (p == 1) ? g_Blo : g_Bhi;
    const __nv_bfloat16* Abase = Asrc + (size_t)m0 * KPAD + k0;
    const __nv_bfloat16* Bbase = Bsrc + (size_t)n0 * KPAD + k0;
    // A tile: 128 rows x 128 B -> 1024 16B units; B same into sbuf+TILEB
#pragma unroll
    for (int i = 0; i < 4; ++i) {
        int u = tid + i * 256;
        int r = u >> 3, w = u & 7;
        u32 off = (u32)(r * 128 + w * 16);
        u32 sw  = off ^ ((off >> 3) & 0x70);
        cpa16(sbuf + sw,         Abase + (size_t)r * KPAD + w * 8);
        cpa16(sbuf + TILEB + sw, Bbase + (size_t)r * KPAD + w * 8);
    }
}

__global__ void __launch_bounds__(256)
gemm_kernel(float* __restrict__ out, int nrows) {
    extern __shared__ char smraw[];
    u32 sm = (u32)__cvta_generic_to_shared(smraw);

    const int tid  = threadIdx.x;
    const int wid  = tid >> 5;
    const int lane = tid & 31;
    const int m0   = (int)blockIdx.y * MT;
    const int n0   = (int)blockIdx.x * NT;

    const int wm = (wid >> 2) * 64;   // warp M offset (2 warps in M)
    const int wn = (wid & 3) * 32;    // warp N offset (4 warps in N)

    const int grp = lane >> 3;
    const int lr  = lane & 7;

    // ldmatrix per-lane address components (byte offsets within a 128x64 bf16 tile)
    // A, m-tile i: row = wm + i*16 + (grp&1)*8 + lr ; sub = grp>>1
    u32 a_rowt[4], a_xor[4];
#pragma unroll
    for (int i = 0; i < 4; ++i) {
        int row = wm + i * 16 + (grp & 1) * 8 + lr;
        a_rowt[i] = (u32)(row * 128);
        a_xor[i]  = (u32)((row & 7) << 4);
    }
    const u32 a_sub16 = (u32)((grp >> 1) * 16);
    // B, n-tile pair j: n = wn + j*16 + (grp>>1)*8 + lr ; sub = grp&1
    u32 b_rowt[2], b_xor[2];
#pragma unroll
    for (int j = 0; j < 2; ++j) {
        int n = wn + j * 16 + (grp >> 1) * 8 + lr;
        b_rowt[j] = (u32)(n * 128);
        b_xor[j]  = (u32)((n & 7) << 4);
    }
    const u32 b_sub16 = (u32)((grp & 1) * 16);

    float acc[4][4][4];
#pragma unroll
    for (int i = 0; i < 4; ++i)
#pragma unroll
        for (int t = 0; t < 4; ++t)
#pragma unroll
            for (int q = 0; q < 4; ++q) acc[i][t][q] = 0.0f;

    // prologue
    stage_chunk(0, sm, m0, n0, tid);
    asm volatile("cp.async.commit_group;" ::: "memory");

#pragma unroll 1
    for (int c = 0; c < NCHK; ++c) {
        u32 cur = sm + (u32)(c & 1) * BUFSZ;
        if (c + 1 < NCHK) {
            stage_chunk(c + 1, sm + (u32)((c + 1) & 1) * BUFSZ, m0, n0, tid);
            asm volatile("cp.async.commit_group;" ::: "memory");
            asm volatile("cp.async.wait_group 1;" ::: "memory");
        } else {
            asm volatile("cp.async.wait_group 0;" ::: "memory");
        }
        __syncthreads();

        u32 sA = cur, sB = cur + TILEB;
#pragma unroll
        for (int ks = 0; ks < 4; ++ks) {
            const u32 ks32 = (u32)(ks * 32);
            u32 a[4][4];
#pragma unroll
            for (int i = 0; i < 4; ++i)
                ldm4(sA + a_rowt[i] + ((ks32 + a_sub16) ^ a_xor[i]),
                     a[i][0], a[i][1], a[i][2], a[i][3]);
            u32 b[4][2];
#pragma unroll
            for (int j = 0; j < 2; ++j) {
                u32 r0, r1, r2, r3;
                ldm4(sB + b_rowt[j] + ((ks32 + b_sub16) ^ b_xor[j]), r0, r1, r2, r3);
                b[2 * j][0] = r0;     b[2 * j][1] = r1;
                b[2 * j + 1][0] = r2; b[2 * j + 1][1] = r3;
            }
#pragma unroll
            for (int i = 0; i < 4; ++i)
#pragma unroll
                for (int t = 0; t < 4; ++t)
                    mma16816(acc[i][t], a[i], b[t]);
        }
        __syncthreads();
    }

    // epilogue: c0,c1 -> (row, col..col+1) ; c2,c3 -> (row+8, ...)
    const int gid = lane >> 2;
    const int tc  = (lane & 3) * 2;
#pragma unroll
    for (int i = 0; i < 4; ++i) {
        int row = m0 + wm + i * 16 + gid;
        if (row >= nrows) continue;
        float* orow = out + (size_t)row * DET;
        float* orow8 = orow + (size_t)8 * DET;
        bool r8ok = (row + 8) < nrows;
#pragma unroll
        for (int t = 0; t < 4; ++t) {
            int col = n0 + wn + t * 8 + tc;
            if (col < DET) {
                *(float2*)(orow + col) = make_float2(acc[i][t][0], acc[i][t][1]);
                if (r8ok)
                    *(float2*)(orow8 + col) = make_float2(acc[i][t][2], acc[i][t][3]);
            }
        }
    }
}

extern "C" void kernel_launch(void* const* d_in, const int* in_sizes, int n_in,
                              void* d_out, int out_size) {
    const float* sino  = (const float*)d_in[0];
    const float* filt  = (const float*)d_in[1];
    const int*   scale = (const int*)d_in[2];
    float* out = (float*)d_out;

    int nrows  = in_sizes[0] / DET;             // 18432
    int mtiles = (nrows + MT - 1) / MT;         // 144
    int ntiles = NPADDED / NT;                  // 6

    static int inited = 0;
    if (!inited) {
        cudaFuncSetAttribute(gemm_kernel,
                             cudaFuncAttributeMaxDynamicSharedMemorySize, SMEM_DYN);
        inited = 1;
    }

    prep_B<<<NPADDED, 192>>>(filt);
    prep_A<<<nrows, 192>>>(sino, scale, nrows);
    dim3 grid(ntiles, mtiles);                  // x fastest: same A rows share L2
    gemm_kernel<<<grid, 256, SMEM_DYN>>>(out, nrows);
}

// round 8
// speedup vs baseline: 3.4573x; 1.3020x over previous
#include <cuda_runtime.h>
#include <cuda_bf16.h>
#include <cstdint>

#define DET      736
#define HDET     368
#define KP       384                      // padded per-parity K / N
#define MAXR     18432
#define MT       128
#define NT       128
#define KCH      64
#define NKC      6                        // K chunks per plane (384/64)
#define NCHK     18                       // 3 planes * 6
#define TILEB    16384                    // 128 rows * 128 B
#define BUFSZ    (2 * TILEB)
#define SMEM_DYN (2 * BUFSZ)              // 64 KB
#define MT_HALF  144                      // m-tiles per parity (18432/128)

typedef uint32_t u32;

// parity-split weighted sinogram, bf16 hi/lo + fp32 copy for the diagonal term
__device__ __nv_bfloat16 g_Aeh[(size_t)MAXR * KP];
__device__ __nv_bfloat16 g_Ael[(size_t)MAXR * KP];
__device__ __nv_bfloat16 g_Aoh[(size_t)MAXR * KP];
__device__ __nv_bfloat16 g_Aol[(size_t)MAXR * KP];
__device__ float         g_Xwe[(size_t)MAXR * KP];
__device__ float         g_Xwo[(size_t)MAXR * KP];
// two parity Toeplitz matrices, bf16 hi/lo: [q][n'][k']
__device__ __nv_bfloat16 g_Bh[2 * KP * KP];
__device__ __nv_bfloat16 g_Bl[2 * KP * KP];

__device__ __forceinline__ void cpa16(u32 s, const void* g) {
    asm volatile("cp.async.cg.shared.global [%0], [%1], 16;" :: "r"(s), "l"(g));
}
__device__ __forceinline__ void ldm4(u32 a, u32& r0, u32& r1, u32& r2, u32& r3) {
    asm volatile("ldmatrix.sync.aligned.m8n8.x4.shared.b16 {%0,%1,%2,%3}, [%4];"
                 : "=r"(r0), "=r"(r1), "=r"(r2), "=r"(r3) : "r"(a));
}
__device__ __forceinline__ void mma16816(float* c, const u32* a, const u32* b) {
    asm volatile(
        "mma.sync.aligned.m16n8k16.row.col.f32.bf16.bf16.f32 "
        "{%0,%1,%2,%3}, {%4,%5,%6,%7}, {%8,%9}, {%0,%1,%2,%3};"
        : "+f"(c[0]), "+f"(c[1]), "+f"(c[2]), "+f"(c[3])
        : "r"(a[0]), "r"(a[1]), "r"(a[2]), "r"(a[3]), "r"(b[0]), "r"(b[1]));
}

// ----------------- prep kernels -----------------

// C0[n'][k'] = filt[736 + 2(k'-n')]  (even outputs vs odd inputs)
// C1[n'][k'] = filt[734 + 2(k'-n')]  (odd outputs vs even inputs)
__global__ void prep_B(const float* __restrict__ filt) {
    int b  = blockIdx.x;                  // 0..767
    int q  = b >> 9 ? 1 : (b >= 384);     // q = b/384
    int np = b - q * 384;
    int tid = threadIdx.x;                // 192
    size_t o = ((size_t)q * KP + np) * KP;
#pragma unroll
    for (int i = 0; i < 2; ++i) {
        int kp = tid + i * 192;           // 0..383
        float v = 0.0f;
        if (np < HDET && kp < HDET) {
            int idx = (q ? 734 : 736) + 2 * (kp - np);
            v = filt[idx];
        }
        __nv_bfloat16 h = __float2bfloat16(v);
        float rem = v - __bfloat162float(h);
        g_Bh[o + kp] = h;
        g_Bl[o + kp] = __float2bfloat16(rem);
    }
}

__global__ void prep_A(const float* __restrict__ x, const int* __restrict__ scale_p,
                       int nrows) {
    int row = blockIdx.x;
    if (row >= nrows || row >= MAXR) return;
    int tid = threadIdx.x;                // 192
    int s_i = *scale_p;
    float scale = (s_i >= 1 && s_i <= 1024) ? (float)s_i : __int_as_float(s_i);
    const float kk = scale * 1.0e-3f;
    const float* xr = x + (size_t)row * DET;
    size_t o = (size_t)row * KP;
#pragma unroll
    for (int i = 0; i < 2; ++i) {
        int kp = tid + i * 192;           // 0..383
        float we = 0.0f, wo = 0.0f;
        if (kp < HDET) {
            int ke = 2 * kp, ko = ke + 1;
            we = xr[ke] * (0.05f * cosf(((float)ke - 367.5f) * kk));
            wo = xr[ko] * (0.05f * cosf(((float)ko - 367.5f) * kk));
        }
        __nv_bfloat16 eh = __float2bfloat16(we);
        __nv_bfloat16 oh = __float2bfloat16(wo);
        g_Aeh[o + kp] = eh;
        g_Ael[o + kp] = __float2bfloat16(we - __bfloat162float(eh));
        g_Aoh[o + kp] = oh;
        g_Aol[o + kp] = __float2bfloat16(wo - __bfloat162float(oh));
        g_Xwe[o + kp] = we;
        g_Xwo[o + kp] = wo;
    }
}

// ----------------- GEMM kernel -----------------

__device__ __forceinline__ void stage_chunk(int c, u32 sbuf, int row0, int n0,
                                            int q, int tid) {
    int p  = c / NKC;
    int kc = c - p * NKC;
    int k0 = kc * KCH;
    // A operand = OPPOSITE parity of output q
    const __nv_bfloat16* Asrc =
        (q == 0) ? ((p < 2) ? g_Aoh : g_Aol)
                 : ((p < 2) ? g_Aeh : g_Ael);
    const __nv_bfloat16* Bsrc = ((p == 1) ? g_Bl : g_Bh) + (size_t)q * KP * KP;
    const __nv_bfloat16* Abase = Asrc + (size_t)row0 * KP + k0;
    const __nv_bfloat16* Bbase = Bsrc + (size_t)n0 * KP + k0;
#pragma unroll
    for (int i = 0; i < 4; ++i) {
        int u = tid + i * 256;
        int r = u >> 3, w = u & 7;
        u32 off = (u32)(r * 128 + w * 16);
        u32 sw  = off ^ ((off >> 3) & 0x70);
        cpa16(sbuf + sw,         Abase + (size_t)r * KP + w * 8);
        cpa16(sbuf + TILEB + sw, Bbase + (size_t)r * KP + w * 8);
    }
}

__global__ void __launch_bounds__(256)
gemm_kernel(float* __restrict__ out, const float* __restrict__ filt, int nrows) {
    extern __shared__ char smraw[];
    u32 sm = (u32)__cvta_generic_to_shared(smraw);

    const int tid  = threadIdx.x;
    const int wid  = tid >> 5;
    const int lane = tid & 31;

    const int mt   = (int)blockIdx.y;
    const int q    = (mt >= MT_HALF) ? 1 : 0;
    const int row0 = (mt - q * MT_HALF) * MT;
    const int n0   = (int)blockIdx.x * NT;

    const int wm = (wid >> 2) * 64;
    const int wn = (wid & 3) * 32;
    const int grp = lane >> 3;
    const int lr  = lane & 7;

    u32 a_rowt[4], a_xor[4];
#pragma unroll
    for (int i = 0; i < 4; ++i) {
        int row = wm + i * 16 + (grp & 1) * 8 + lr;
        a_rowt[i] = (u32)(row * 128);
        a_xor[i]  = (u32)((row & 7) << 4);
    }
    const u32 a_sub16 = (u32)((grp >> 1) * 16);
    u32 b_rowt[2], b_xor[2];
#pragma unroll
    for (int j = 0; j < 2; ++j) {
        int n = wn + j * 16 + (grp >> 1) * 8 + lr;
        b_rowt[j] = (u32)(n * 128);
        b_xor[j]  = (u32)((n & 7) << 4);
    }
    const u32 b_sub16 = (u32)((grp & 1) * 16);

    float acc[4][4][4];
#pragma unroll
    for (int i = 0; i < 4; ++i)
#pragma unroll
        for (int t = 0; t < 4; ++t)
#pragma unroll
            for (int c2 = 0; c2 < 4; ++c2) acc[i][t][c2] = 0.0f;

    stage_chunk(0, sm, row0, n0, q, tid);
    asm volatile("cp.async.commit_group;" ::: "memory");

#pragma unroll 1
    for (int c = 0; c < NCHK; ++c) {
        u32 cur = sm + (u32)(c & 1) * BUFSZ;
        if (c + 1 < NCHK) {
            stage_chunk(c + 1, sm + (u32)((c + 1) & 1) * BUFSZ, row0, n0, q, tid);
            asm volatile("cp.async.commit_group;" ::: "memory");
            asm volatile("cp.async.wait_group 1;" ::: "memory");
        } else {
            asm volatile("cp.async.wait_group 0;" ::: "memory");
        }
        __syncthreads();

        u32 sA = cur, sB = cur + TILEB;
#pragma unroll
        for (int ks = 0; ks < 4; ++ks) {
            const u32 ks32 = (u32)(ks * 32);
            u32 a[4][4];
#pragma unroll
            for (int i = 0; i < 4; ++i)
                ldm4(sA + a_rowt[i] + ((ks32 + a_sub16) ^ a_xor[i]),
                     a[i][0], a[i][1], a[i][2], a[i][3]);
            u32 b[4][2];
#pragma unroll
            for (int j = 0; j < 2; ++j) {
                u32 r0, r1, r2, r3;
                ldm4(sB + b_rowt[j] + ((ks32 + b_sub16) ^ b_xor[j]), r0, r1, r2, r3);
                b[2 * j][0] = r0;     b[2 * j][1] = r1;
                b[2 * j + 1][0] = r2; b[2 * j + 1][1] = r3;
            }
#pragma unroll
            for (int i = 0; i < 4; ++i)
#pragma unroll
                for (int t = 0; t < 4; ++t)
                    mma16816(acc[i][t], a[i], b[t]);
        }
        __syncthreads();
    }

    // epilogue: out[row][2*col'+q] = acc + h0 * Xw_q[row][col']
    const float h0 = __ldg(&filt[735]);
    const float* Xwp = q ? g_Xwo : g_Xwe;
    const int gid = lane >> 2;
    const int tc  = (lane & 3) * 2;
#pragma unroll
    for (int i = 0; i < 4; ++i) {
        int row = row0 + wm + i * 16 + gid;
        if (row >= nrows) continue;
        float* o0 = out + (size_t)row * DET + q;
        float* o1 = o0 + (size_t)8 * DET;
        const float* xw0 = Xwp + (size_t)row * KP;
        const float* xw1 = xw0 + (size_t)8 * KP;
        bool r8ok = (row + 8) < nrows;
#pragma unroll
        for (int t = 0; t < 4; ++t) {
            int col = n0 + wn + t * 8 + tc;
            if (col < HDET) {
                float2 d0 = *(const float2*)(xw0 + col);
                o0[2 * col]     = acc[i][t][0] + h0 * d0.x;
                o0[2 * col + 2] = acc[i][t][1] + h0 * d0.y;
                if (r8ok) {
                    float2 d1 = *(const float2*)(xw1 + col);
                    o1[2 * col]     = acc[i][t][2] + h0 * d1.x;
                    o1[2 * col + 2] = acc[i][t][3] + h0 * d1.y;
                }
            }
        }
    }
}

extern "C" void kernel_launch(void* const* d_in, const int* in_sizes, int n_in,
                              void* d_out, int out_size) {
    const float* sino  = (const float*)d_in[0];
    const float* filt  = (const float*)d_in[1];
    const int*   scale = (const int*)d_in[2];
    float* out = (float*)d_out;

    int nrows = in_sizes[0] / DET;              // 18432

    static int inited = 0;
    if (!inited) {
        cudaFuncSetAttribute(gemm_kernel,
                             cudaFuncAttributeMaxDynamicSharedMemorySize, SMEM_DYN);
        inited = 1;
    }

    prep_B<<<2 * KP, 192>>>(filt);
    prep_A<<<nrows, 192>>>(sino, scale, nrows);
    dim3 grid(KP / NT, 2 * MT_HALF);            // (3, 288)
    gemm_kernel<<<grid, 256, SMEM_DYN>>>(out, filt, nrows);
}

// round 9
// speedup vs baseline: 4.0188x; 1.1624x over previous
#include <cuda_runtime.h>
#include <cuda_bf16.h>
#include <cstdint>

#define DET      736
#define HDET     368
#define KP       384                      // padded per-parity K / N
#define MAXR     18432
#define MT       128
#define NT       128
#define KCH      64
#define NKC      6                        // K chunks per plane (384/64)
#define NCHK     18                       // 3 planes * 6
#define TILEB    16384                    // 128 rows * 128 B
#define BUFSZ    (2 * TILEB)
#define SMEM_DYN (2 * BUFSZ)              // 64 KB
#define MT_HALF  144                      // m-tiles per parity (18432/128)

typedef uint32_t u32;

// parity-split weighted sinogram, bf16 hi/lo
__device__ __nv_bfloat16 g_Aeh[(size_t)MAXR * KP];
__device__ __nv_bfloat16 g_Ael[(size_t)MAXR * KP];
__device__ __nv_bfloat16 g_Aoh[(size_t)MAXR * KP];
__device__ __nv_bfloat16 g_Aol[(size_t)MAXR * KP];
// two parity Toeplitz matrices, bf16 hi/lo: [q][n'][k']
__device__ __nv_bfloat16 g_Bh[2 * KP * KP];
__device__ __nv_bfloat16 g_Bl[2 * KP * KP];

__device__ __forceinline__ void cpa16(u32 s, const void* g) {
    asm volatile("cp.async.cg.shared.global [%0], [%1], 16;" :: "r"(s), "l"(g));
}
__device__ __forceinline__ void ldm4(u32 a, u32& r0, u32& r1, u32& r2, u32& r3) {
    asm volatile("ldmatrix.sync.aligned.m8n8.x4.shared.b16 {%0,%1,%2,%3}, [%4];"
                 : "=r"(r0), "=r"(r1), "=r"(r2), "=r"(r3) : "r"(a));
}
__device__ __forceinline__ void mma16816(float* c, const u32* a, const u32* b) {
    asm volatile(
        "mma.sync.aligned.m16n8k16.row.col.f32.bf16.bf16.f32 "
        "{%0,%1,%2,%3}, {%4,%5,%6,%7}, {%8,%9}, {%0,%1,%2,%3};"
        : "+f"(c[0]), "+f"(c[1]), "+f"(c[2]), "+f"(c[3])
        : "r"(a[0]), "r"(a[1]), "r"(a[2]), "r"(a[3]), "r"(b[0]), "r"(b[1]));
}
__device__ __forceinline__ u32 pkbf2(float a, float b) {
    u32 r;
    asm("cvt.rn.bf16x2.f32 %0, %1, %2;" : "=r"(r) : "f"(b), "f"(a));
    return r;
}
// sum of two packed bf16 pairs as float2
__device__ __forceinline__ float2 bf2sum(u32 h, u32 l) {
    __nv_bfloat162 hh = *(__nv_bfloat162*)&h;
    __nv_bfloat162 ll = *(__nv_bfloat162*)&l;
    return make_float2(__bfloat162float(hh.x) + __bfloat162float(ll.x),
                       __bfloat162float(hh.y) + __bfloat162float(ll.y));
}

// ----------------- prep kernels -----------------

// C0[n'][k'] = filt[736 + 2(k'-n')]  (even outputs vs odd inputs)
// C1[n'][k'] = filt[734 + 2(k'-n')]  (odd outputs vs even inputs)
__global__ void prep_B(const float* __restrict__ filt) {
    int b  = blockIdx.x;                  // 0..767
    int q  = (b >= KP);
    int np = b - q * KP;
    int tid = threadIdx.x;                // 192
    size_t o = ((size_t)q * KP + np) * KP;
#pragma unroll
    for (int i = 0; i < 2; ++i) {
        int kp = tid + i * 192;           // 0..383
        float v = 0.0f;
        if (np < HDET && kp < HDET) {
            int idx = (q ? 734 : 736) + 2 * (kp - np);
            v = filt[idx];
        }
        __nv_bfloat16 h = __float2bfloat16(v);
        float rem = v - __bfloat162float(h);
        g_Bh[o + kp] = h;
        g_Bl[o + kp] = __float2bfloat16(rem);
    }
}

__global__ void __launch_bounds__(192)
prep_A(const float* __restrict__ x, const int* __restrict__ scale_p, int nrows) {
    int row = blockIdx.x;
    if (row >= nrows || row >= MAXR) return;
    int tid = threadIdx.x;                // 192: each thread does 2 pair-columns
    int s_i = *scale_p;
    float scale = (s_i >= 1 && s_i <= 1024) ? (float)s_i : __int_as_float(s_i);
    const float kk = scale * 1.0e-3f;
    const float4* xr4 = (const float4*)(x + (size_t)row * DET);  // 184 float4s
    size_t o2 = (size_t)row * (KP / 2);   // u32-pair granularity
    u32* Aeh2 = (u32*)g_Aeh + o2;  u32* Ael2 = (u32*)g_Ael + o2;
    u32* Aoh2 = (u32*)g_Aoh + o2;  u32* Aol2 = (u32*)g_Aol + o2;

    int p = tid;                           // pair-column 0..191 (of 192 = KP/2)
    float4 v;
    if (2 * p < HDET) v = xr4[p];          // detectors 4p..4p+3
    else v = make_float4(0.f, 0.f, 0.f, 0.f);
    float base = (float)(4 * p) - 367.5f;
    float we0 = v.x * (0.05f * __cosf(base * kk));
    float wo0 = v.y * (0.05f * __cosf((base + 1.0f) * kk));
    float we1 = v.z * (0.05f * __cosf((base + 2.0f) * kk));
    float wo1 = v.w * (0.05f * __cosf((base + 3.0f) * kk));

    u32 eh = pkbf2(we0, we1), oh = pkbf2(wo0, wo1);
    __nv_bfloat162 ehv = *(__nv_bfloat162*)&eh;
    __nv_bfloat162 ohv = *(__nv_bfloat162*)&oh;
    u32 el = pkbf2(we0 - __bfloat162float(ehv.x), we1 - __bfloat162float(ehv.y));
    u32 ol = pkbf2(wo0 - __bfloat162float(ohv.x), wo1 - __bfloat162float(ohv.y));
    Aeh2[p] = eh; Ael2[p] = el; Aoh2[p] = oh; Aol2[p] = ol;
}

// ----------------- GEMM kernel -----------------

__device__ __forceinline__ void stage_chunk(int c, u32 sbuf, int row0, int n0,
                                            int q, int tid) {
    int p  = c / NKC;
    int kc = c - p * NKC;
    int k0 = kc * KCH;
    // A operand = OPPOSITE parity of output q
    const __nv_bfloat16* Asrc =
        (q == 0) ? ((p < 2) ? g_Aoh : g_Aol)
                 : ((p < 2) ? g_Aeh : g_Ael);
    const __nv_bfloat16* Bsrc = ((p == 1) ? g_Bl : g_Bh) + (size_t)q * KP * KP;
    const __nv_bfloat16* Abase = Asrc + (size_t)row0 * KP + k0;
    const __nv_bfloat16* Bbase = Bsrc + (size_t)n0 * KP + k0;
#pragma unroll
    for (int i = 0; i < 4; ++i) {
        int u = tid + i * 256;
        int r = u >> 3, w = u & 7;
        u32 off = (u32)(r * 128 + w * 16);
        u32 sw  = off ^ ((off >> 3) & 0x70);
        cpa16(sbuf + sw,         Abase + (size_t)r * KP + w * 8);
        cpa16(sbuf + TILEB + sw, Bbase + (size_t)r * KP + w * 8);
    }
}

__global__ void __launch_bounds__(256)
gemm_kernel(float* __restrict__ out, const float* __restrict__ filt, int nrows) {
    extern __shared__ char smraw[];
    u32 sm = (u32)__cvta_generic_to_shared(smraw);

    const int tid  = threadIdx.x;
    const int wid  = tid >> 5;
    const int lane = tid & 31;

    // parity CTAs for the same rows are ADJACENT in blockIdx.y -> co-resident
    // -> their complementary half-sector output writes merge in L2
    const int q    = (int)blockIdx.y & 1;
    const int row0 = ((int)blockIdx.y >> 1) * MT;
    const int n0   = (int)blockIdx.x * NT;

    const int wm = (wid >> 2) * 64;
    const int wn = (wid & 3) * 32;
    const int grp = lane >> 3;
    const int lr  = lane & 7;

    u32 a_rowt[4], a_xor[4];
#pragma unroll
    for (int i = 0; i < 4; ++i) {
        int row = wm + i * 16 + (grp & 1) * 8 + lr;
        a_rowt[i] = (u32)(row * 128);
        a_xor[i]  = (u32)((row & 7) << 4);
    }
    const u32 a_sub16 = (u32)((grp >> 1) * 16);
    u32 b_rowt[2], b_xor[2];
#pragma unroll
    for (int j = 0; j < 2; ++j) {
        int n = wn + j * 16 + (grp >> 1) * 8 + lr;
        b_rowt[j] = (u32)(n * 128);
        b_xor[j]  = (u32)((n & 7) << 4);
    }
    const u32 b_sub16 = (u32)((grp & 1) * 16);

    float acc[4][4][4];
#pragma unroll
    for (int i = 0; i < 4; ++i)
#pragma unroll
        for (int t = 0; t < 4; ++t)
#pragma unroll
            for (int c2 = 0; c2 < 4; ++c2) acc[i][t][c2] = 0.0f;

    stage_chunk(0, sm, row0, n0, q, tid);
    asm volatile("cp.async.commit_group;" ::: "memory");

#pragma unroll 1
    for (int c = 0; c < NCHK; ++c) {
        u32 cur = sm + (u32)(c & 1) * BUFSZ;
        if (c + 1 < NCHK) {
            stage_chunk(c + 1, sm + (u32)((c + 1) & 1) * BUFSZ, row0, n0, q, tid);
            asm volatile("cp.async.commit_group;" ::: "memory");
            asm volatile("cp.async.wait_group 1;" ::: "memory");
        } else {
            asm volatile("cp.async.wait_group 0;" ::: "memory");
        }
        __syncthreads();

        u32 sA = cur, sB = cur + TILEB;
#pragma unroll
        for (int ks = 0; ks < 4; ++ks) {
            const u32 ks32 = (u32)(ks * 32);
            u32 a[4][4];
#pragma unroll
            for (int i = 0; i < 4; ++i)
                ldm4(sA + a_rowt[i] + ((ks32 + a_sub16) ^ a_xor[i]),
                     a[i][0], a[i][1], a[i][2], a[i][3]);
            u32 b[4][2];
#pragma unroll
            for (int j = 0; j < 2; ++j) {
                u32 r0, r1, r2, r3;
                ldm4(sB + b_rowt[j] + ((ks32 + b_sub16) ^ b_xor[j]), r0, r1, r2, r3);
                b[2 * j][0] = r0;     b[2 * j][1] = r1;
                b[2 * j + 1][0] = r2; b[2 * j + 1][1] = r3;
            }
#pragma unroll
            for (int i = 0; i < 4; ++i)
#pragma unroll
                for (int t = 0; t < 4; ++t)
                    mma16816(acc[i][t], a[i], b[t]);
        }
        __syncthreads();
    }

    // epilogue: out[row][2*col'+q] = acc + h0 * (Ahi_q + Alo_q)[row][col']
    const float h0 = __ldg(&filt[735]);
    const u32* Ah2 = (const u32*)(q ? g_Aoh : g_Aeh);
    const u32* Al2 = (const u32*)(q ? g_Aol : g_Ael);
    const int gid = lane >> 2;
    const int tc  = (lane & 3) * 2;
#pragma unroll
    for (int i = 0; i < 4; ++i) {
        int row = row0 + wm + i * 16 + gid;
        if (row >= nrows) continue;
        float* o0 = out + (size_t)row * DET + q;
        float* o1 = o0 + (size_t)8 * DET;
        const u32* ah0 = Ah2 + (size_t)row * (KP / 2);
        const u32* al0 = Al2 + (size_t)row * (KP / 2);
        bool r8ok = (row + 8) < nrows;
#pragma unroll
        for (int t = 0; t < 4; ++t) {
            int col = n0 + wn + t * 8 + tc;          // even: pair index col/2
            if (col < HDET) {
                float2 d0 = bf2sum(ah0[col >> 1], al0[col >> 1]);
                o0[2 * col]     = acc[i][t][0] + h0 * d0.x;
                o0[2 * col + 2] = acc[i][t][1] + h0 * d0.y;
                if (r8ok) {
                    float2 d1 = bf2sum(ah0[(col >> 1) + 4 * KP / 2 * 2 / 2],
                                       al0[(col >> 1) + 4 * KP]);
                    // (replaced below — see r8 path)
                    d1 = bf2sum(*(ah0 + 8 * (KP / 2) + (col >> 1)),
                                *(al0 + 8 * (KP / 2) + (col >> 1)));
                    o1[2 * col]     = acc[i][t][2] + h0 * d1.x;
                    o1[2 * col + 2] = acc[i][t][3] + h0 * d1.y;
                }
            }
        }
    }
}

extern "C" void kernel_launch(void* const* d_in, const int* in_sizes, int n_in,
                              void* d_out, int out_size) {
    const float* sino  = (const float*)d_in[0];
    const float* filt  = (const float*)d_in[1];
    const int*   scale = (const int*)d_in[2];
    float* out = (float*)d_out;

    int nrows = in_sizes[0] / DET;              // 18432

    static int inited = 0;
    if (!inited) {
        cudaFuncSetAttribute(gemm_kernel,
                             cudaFuncAttributeMaxDynamicSharedMemorySize, SMEM_DYN);
        inited = 1;
    }

    prep_B<<<2 * KP, 192>>>(filt);
    prep_A<<<nrows, 192>>>(sino, scale, nrows);
    dim3 grid(KP / NT, 2 * MT_HALF);            // (3, 288), parity pairs adjacent
    gemm_kernel<<<grid, 256, SMEM_DYN>>>(out, filt, nrows);
}

// round 10
// speedup vs baseline: 5.7721x; 1.4363x over previous
#include <cuda_runtime.h>
#include <cuda_fp16.h>
#include <cstdint>

#define DET      736
#define HDET     368
#define KP       384                      // padded per-parity K / N
#define MAXR     18432
#define MT       128
#define NT       128
#define KCH      64
#define NCHK     6                        // merged chunks (A,Bhi,Blo per 64-K slice)
#define TILEB    16384                    // 128 rows * 128 B
#define BUFSZ    (3 * TILEB)              // A + Bhi + Blo per stage = 48 KB
#define SMEM_DYN (2 * BUFSZ)              // 96 KB double-buffered
#define MT_HALF  144                      // m-tiles per parity (18432/128)

typedef uint32_t u32;

// parity-split weighted sinogram, single fp16 plane
__device__ __half g_Ae[(size_t)MAXR * KP];
__device__ __half g_Ao[(size_t)MAXR * KP];
// two parity Toeplitz matrices, fp16 hi/lo: [q][n'][k']
__device__ __half g_Bh[2 * KP * KP];
__device__ __half g_Bl[2 * KP * KP];

__device__ __forceinline__ void cpa16(u32 s, const void* g) {
    asm volatile("cp.async.cg.shared.global [%0], [%1], 16;" :: "r"(s), "l"(g));
}
__device__ __forceinline__ void ldm4(u32 a, u32& r0, u32& r1, u32& r2, u32& r3) {
    asm volatile("ldmatrix.sync.aligned.m8n8.x4.shared.b16 {%0,%1,%2,%3}, [%4];"
                 : "=r"(r0), "=r"(r1), "=r"(r2), "=r"(r3) : "r"(a));
}
__device__ __forceinline__ void mma16816(float* c, const u32* a, const u32* b) {
    asm volatile(
        "mma.sync.aligned.m16n8k16.row.col.f32.f16.f16.f32 "
        "{%0,%1,%2,%3}, {%4,%5,%6,%7}, {%8,%9}, {%0,%1,%2,%3};"
        : "+f"(c[0]), "+f"(c[1]), "+f"(c[2]), "+f"(c[3])
        : "r"(a[0]), "r"(a[1]), "r"(a[2]), "r"(a[3]), "r"(b[0]), "r"(b[1]));
}
__device__ __forceinline__ u32 pkhf2(float a, float b) {
    u32 r;
    asm("cvt.rn.f16x2.f32 %0, %1, %2;" : "=r"(r) : "f"(b), "f"(a));
    return r;
}
__device__ __forceinline__ float2 hf2f(u32 h) {
    __half2 v = *(__half2*)&h;
    return make_float2(__half2float(v.x), __half2float(v.y));
}

// ----------------- prep kernels -----------------

// C0[n'][k'] = filt[736 + 2(k'-n')]  (even outputs vs odd inputs)
// C1[n'][k'] = filt[734 + 2(k'-n')]  (odd outputs vs even inputs)
__global__ void prep_B(const float* __restrict__ filt) {
    int b  = blockIdx.x;                  // 0..767
    int q  = (b >= KP);
    int np = b - q * KP;
    int tid = threadIdx.x;                // 192
    size_t o = ((size_t)q * KP + np) * KP;
#pragma unroll
    for (int i = 0; i < 2; ++i) {
        int kp = tid + i * 192;           // 0..383
        float v = 0.0f;
        if (np < HDET && kp < HDET) {
            int idx = (q ? 734 : 736) + 2 * (kp - np);
            v = filt[idx];
        }
        __half h = __float2half(v);
        g_Bh[o + kp] = h;
        g_Bl[o + kp] = __float2half(v - __half2float(h));
    }
}

__global__ void __launch_bounds__(192)
prep_A(const float* __restrict__ x, const int* __restrict__ scale_p, int nrows) {
    int row = blockIdx.x;
    if (row >= nrows || row >= MAXR) return;
    int tid = threadIdx.x;                // 192 = KP/2 pair-columns
    int s_i = *scale_p;
    float scale = (s_i >= 1 && s_i <= 1024) ? (float)s_i : __int_as_float(s_i);
    const float kk = scale * 1.0e-3f;
    const float4* xr4 = (const float4*)(x + (size_t)row * DET);
    size_t o2 = (size_t)row * (KP / 2);
    u32* Ae2 = (u32*)g_Ae + o2;
    u32* Ao2 = (u32*)g_Ao + o2;

    int p = tid;                           // covers detectors 4p..4p+3
    float4 v;
    if (2 * p < HDET) v = xr4[p];
    else v = make_float4(0.f, 0.f, 0.f, 0.f);
    float base = (float)(4 * p) - 367.5f;
    float we0 = v.x * (0.05f * __cosf(base * kk));
    float wo0 = v.y * (0.05f * __cosf((base + 1.0f) * kk));
    float we1 = v.z * (0.05f * __cosf((base + 2.0f) * kk));
    float wo1 = v.w * (0.05f * __cosf((base + 3.0f) * kk));

    Ae2[p] = pkhf2(we0, we1);
    Ao2[p] = pkhf2(wo0, wo1);
}

// ----------------- GEMM kernel -----------------

// stage merged chunk kc: A(16KB) + Bhi(16KB) + Blo(16KB)
__device__ __forceinline__ void stage_chunk(int kc, u32 sbuf, int row0, int n0,
                                            int q, int tid) {
    int k0 = kc * KCH;
    const __half* Abase = ((q == 0) ? g_Ao : g_Ae) + (size_t)row0 * KP + k0;
    size_t bo = (size_t)q * KP * KP + (size_t)n0 * KP + k0;
    const __half* Bh = g_Bh + bo;
    const __half* Bl = g_Bl + bo;
#pragma unroll
    for (int i = 0; i < 4; ++i) {
        int u = tid + i * 256;
        int r = u >> 3, w = u & 7;
        u32 off = (u32)(r * 128 + w * 16);
        u32 sw  = off ^ ((off >> 3) & 0x70);
        const size_t go = (size_t)r * KP + w * 8;
        cpa16(sbuf + sw,             Abase + go);
        cpa16(sbuf + TILEB + sw,     Bh + go);
        cpa16(sbuf + 2 * TILEB + sw, Bl + go);
    }
}

__global__ void __launch_bounds__(256, 2)
gemm_kernel(float* __restrict__ out, const float* __restrict__ filt, int nrows) {
    extern __shared__ char smraw[];
    u32 sm = (u32)__cvta_generic_to_shared(smraw);

    const int tid  = threadIdx.x;
    const int wid  = tid >> 5;
    const int lane = tid & 31;

    // parity CTAs for the same rows adjacent in blockIdx.y -> co-resident,
    // complementary half-sector output writes merge in L2
    const int q    = (int)blockIdx.y & 1;
    const int row0 = ((int)blockIdx.y >> 1) * MT;
    const int n0   = (int)blockIdx.x * NT;

    const int wm = (wid >> 2) * 64;
    const int wn = (wid & 3) * 32;
    const int grp = lane >> 3;
    const int lr  = lane & 7;

    u32 a_rowt[4], a_xor[4];
#pragma unroll
    for (int i = 0; i < 4; ++i) {
        int row = wm + i * 16 + (grp & 1) * 8 + lr;
        a_rowt[i] = (u32)(row * 128);
        a_xor[i]  = (u32)((row & 7) << 4);
    }
    const u32 a_sub16 = (u32)((grp >> 1) * 16);
    u32 b_rowt[2], b_xor[2];
#pragma unroll
    for (int j = 0; j < 2; ++j) {
        int n = wn + j * 16 + (grp >> 1) * 8 + lr;
        b_rowt[j] = (u32)(n * 128);
        b_xor[j]  = (u32)((n & 7) << 4);
    }
    const u32 b_sub16 = (u32)((grp & 1) * 16);

    float acc[4][4][4];
#pragma unroll
    for (int i = 0; i < 4; ++i)
#pragma unroll
        for (int t = 0; t < 4; ++t)
#pragma unroll
            for (int c2 = 0; c2 < 4; ++c2) acc[i][t][c2] = 0.0f;

    stage_chunk(0, sm, row0, n0, q, tid);
    asm volatile("cp.async.commit_group;" ::: "memory");

#pragma unroll 1
    for (int c = 0; c < NCHK; ++c) {
        u32 cur = sm + (u32)(c & 1) * BUFSZ;
        if (c + 1 < NCHK) {
            stage_chunk(c + 1, sm + (u32)((c + 1) & 1) * BUFSZ, row0, n0, q, tid);
            asm volatile("cp.async.commit_group;" ::: "memory");
            asm volatile("cp.async.wait_group 1;" ::: "memory");
        } else {
            asm volatile("cp.async.wait_group 0;" ::: "memory");
        }
        __syncthreads();

        u32 sA = cur, sBh = cur + TILEB, sBl = cur + 2 * TILEB;
#pragma unroll
        for (int ks = 0; ks < 4; ++ks) {
            const u32 ks32 = (u32)(ks * 32);
            u32 a[4][4];
#pragma unroll
            for (int i = 0; i < 4; ++i)
                ldm4(sA + a_rowt[i] + ((ks32 + a_sub16) ^ a_xor[i]),
                     a[i][0], a[i][1], a[i][2], a[i][3]);
            // plane hi
            {
                u32 b[4][2];
#pragma unroll
                for (int j = 0; j < 2; ++j) {
                    u32 r0, r1, r2, r3;
                    ldm4(sBh + b_rowt[j] + ((ks32 + b_sub16) ^ b_xor[j]), r0, r1, r2, r3);
                    b[2 * j][0] = r0;     b[2 * j][1] = r1;
                    b[2 * j + 1][0] = r2; b[2 * j + 1][1] = r3;
                }
#pragma unroll
                for (int i = 0; i < 4; ++i)
#pragma unroll
                    for (int t = 0; t < 4; ++t)
                        mma16816(acc[i][t], a[i], b[t]);
            }
            // plane lo (reuse A fragments)
            {
                u32 b[4][2];
#pragma unroll
                for (int j = 0; j < 2; ++j) {
                    u32 r0, r1, r2, r3;
                    ldm4(sBl + b_rowt[j] + ((ks32 + b_sub16) ^ b_xor[j]), r0, r1, r2, r3);
                    b[2 * j][0] = r0;     b[2 * j][1] = r1;
                    b[2 * j + 1][0] = r2; b[2 * j + 1][1] = r3;
                }
#pragma unroll
                for (int i = 0; i < 4; ++i)
#pragma unroll
                    for (int t = 0; t < 4; ++t)
                        mma16816(acc[i][t], a[i], b[t]);
            }
        }
        __syncthreads();
    }

    // epilogue: out[row][2*col'+q] = acc + h0 * A_q[row][col']
    const float h0 = __ldg(&filt[735]);
    const u32* A2 = (const u32*)(q ? g_Ao : g_Ae);
    const int gid = lane >> 2;
    const int tc  = (lane & 3) * 2;
#pragma unroll
    for (int i = 0; i < 4; ++i) {
        int row = row0 + wm + i * 16 + gid;
        if (row >= nrows) continue;
        float* o0 = out + (size_t)row * DET + q;
        float* o1 = o0 + (size_t)8 * DET;
        const u32* a0 = A2 + (size_t)row * (KP / 2);
        const u32* a1 = a0 + (size_t)8 * (KP / 2);
        bool r8ok = (row + 8) < nrows;
#pragma unroll
        for (int t = 0; t < 4; ++t) {
            int col = n0 + wn + t * 8 + tc;          // even; pair idx col/2
            if (col < HDET) {
                float2 d0 = hf2f(a0[col >> 1]);
                o0[2 * col]     = acc[i][t][0] + h0 * d0.x;
                o0[2 * col + 2] = acc[i][t][1] + h0 * d0.y;
                if (r8ok) {
                    float2 d1 = hf2f(a1[col >> 1]);
                    o1[2 * col]     = acc[i][t][2] + h0 * d1.x;
                    o1[2 * col + 2] = acc[i][t][3] + h0 * d1.y;
                }
            }
        }
    }
}

extern "C" void kernel_launch(void* const* d_in, const int* in_sizes, int n_in,
                              void* d_out, int out_size) {
    const float* sino  = (const float*)d_in[0];
    const float* filt  = (const float*)d_in[1];
    const int*   scale = (const int*)d_in[2];
    float* out = (float*)d_out;

    int nrows = in_sizes[0] / DET;              // 18432

    static int inited = 0;
    if (!inited) {
        cudaFuncSetAttribute(gemm_kernel,
                             cudaFuncAttributeMaxDynamicSharedMemorySize, SMEM_DYN);
        inited = 1;
    }

    prep_B<<<2 * KP, 192>>>(filt);
    prep_A<<<nrows, 192>>>(sino, scale, nrows);
    dim3 grid(KP / NT, 2 * MT_HALF);            // (3, 288)
    gemm_kernel<<<grid, 256, SMEM_DYN>>>(out, filt, nrows);
}

// round 11
// speedup vs baseline: 7.1244x; 1.2343x over previous
#include <cuda_runtime.h>
#include <cuda_fp16.h>
#include <cstdint>

#define DET      736
#define HDET     368
#define KP       384                      // padded per-parity K / N
#define MAXR     18432
#define MT       128
#define NT       128
#define KCH      64
#define NCHK     6                        // 64-K chunks (384/64)
#define TILEB    16384                    // 128 rows * 128 B
#define BUFSZ    (2 * TILEB)              // A + B per stage = 32 KB
#define SMEM_DYN (2 * BUFSZ)              // 64 KB double-buffered
#define MT_HALF  144                      // m-tiles per parity (18432/128)

typedef uint32_t u32;

// parity-split weighted sinogram, single fp16 plane
__device__ __half g_Ae[(size_t)MAXR * KP];
__device__ __half g_Ao[(size_t)MAXR * KP];
// two parity Toeplitz matrices, single fp16 plane: [q][n'][k']
__device__ __half g_Bh[2 * KP * KP];

__device__ __forceinline__ void cpa16(u32 s, const void* g) {
    asm volatile("cp.async.cg.shared.global [%0], [%1], 16;" :: "r"(s), "l"(g));
}
__device__ __forceinline__ void ldm4(u32 a, u32& r0, u32& r1, u32& r2, u32& r3) {
    asm volatile("ldmatrix.sync.aligned.m8n8.x4.shared.b16 {%0,%1,%2,%3}, [%4];"
                 : "=r"(r0), "=r"(r1), "=r"(r2), "=r"(r3) : "r"(a));
}
__device__ __forceinline__ void mma16816(float* c, const u32* a, const u32* b) {
    asm volatile(
        "mma.sync.aligned.m16n8k16.row.col.f32.f16.f16.f32 "
        "{%0,%1,%2,%3}, {%4,%5,%6,%7}, {%8,%9}, {%0,%1,%2,%3};"
        : "+f"(c[0]), "+f"(c[1]), "+f"(c[2]), "+f"(c[3])
        : "r"(a[0]), "r"(a[1]), "r"(a[2]), "r"(a[3]), "r"(b[0]), "r"(b[1]));
}
__device__ __forceinline__ u32 pkhf2(float a, float b) {
    u32 r;
    asm("cvt.rn.f16x2.f32 %0, %1, %2;" : "=r"(r) : "f"(b), "f"(a));
    return r;
}
__device__ __forceinline__ float2 hf2f(u32 h) {
    __half2 v = *(__half2*)&h;
    return make_float2(__half2float(v.x), __half2float(v.y));
}

// ----------------- prep kernels -----------------

// C0[n'][k'] = filt[736 + 2(k'-n')]  (even outputs vs odd inputs)
// C1[n'][k'] = filt[734 + 2(k'-n')]  (odd outputs vs even inputs)
__global__ void prep_B(const float* __restrict__ filt) {
    int b  = blockIdx.x;                  // 0..767
    int q  = (b >= KP);
    int np = b - q * KP;
    int tid = threadIdx.x;                // 192
    size_t o = ((size_t)q * KP + np) * KP;
#pragma unroll
    for (int i = 0; i < 2; ++i) {
        int kp = tid + i * 192;           // 0..383
        float v = 0.0f;
        if (np < HDET && kp < HDET) {
            int idx = (q ? 734 : 736) + 2 * (kp - np);
            v = filt[idx];
        }
        g_Bh[o + kp] = __float2half(v);
    }
}

__global__ void __launch_bounds__(192)
prep_A(const float* __restrict__ x, const int* __restrict__ scale_p, int nrows) {
    int row = blockIdx.x;
    if (row >= nrows || row >= MAXR) return;
    int tid = threadIdx.x;                // 192 = KP/2 pair-columns
    int s_i = *scale_p;
    float scale = (s_i >= 1 && s_i <= 1024) ? (float)s_i : __int_as_float(s_i);
    const float kk = scale * 1.0e-3f;
    const float4* xr4 = (const float4*)(x + (size_t)row * DET);
    size_t o2 = (size_t)row * (KP / 2);
    u32* Ae2 = (u32*)g_Ae + o2;
    u32* Ao2 = (u32*)g_Ao + o2;

    int p = tid;                           // covers detectors 4p..4p+3
    float4 v;
    if (2 * p < HDET) v = xr4[p];
    else v = make_float4(0.f, 0.f, 0.f, 0.f);
    float base = (float)(4 * p) - 367.5f;
    float we0 = v.x * (0.05f * __cosf(base * kk));
    float wo0 = v.y * (0.05f * __cosf((base + 1.0f) * kk));
    float we1 = v.z * (0.05f * __cosf((base + 2.0f) * kk));
    float wo1 = v.w * (0.05f * __cosf((base + 3.0f) * kk));

    Ae2[p] = pkhf2(we0, we1);
    Ao2[p] = pkhf2(wo0, wo1);
}

// ----------------- GEMM kernel -----------------

// stage chunk kc: A(16KB) + B(16KB)
__device__ __forceinline__ void stage_chunk(int kc, u32 sbuf, int row0, int n0,
                                            int q, int tid) {
    int k0 = kc * KCH;
    const __half* Abase = ((q == 0) ? g_Ao : g_Ae) + (size_t)row0 * KP + k0;
    const __half* Bbase = g_Bh + (size_t)q * KP * KP + (size_t)n0 * KP + k0;
#pragma unroll
    for (int i = 0; i < 4; ++i) {
        int u = tid + i * 256;
        int r = u >> 3, w = u & 7;
        u32 off = (u32)(r * 128 + w * 16);
        u32 sw  = off ^ ((off >> 3) & 0x70);
        const size_t go = (size_t)r * KP + w * 8;
        cpa16(sbuf + sw,         Abase + go);
        cpa16(sbuf + TILEB + sw, Bbase + go);
    }
}

__global__ void __launch_bounds__(256, 2)
gemm_kernel(float* __restrict__ out, const float* __restrict__ filt, int nrows) {
    extern __shared__ char smraw[];
    u32 sm = (u32)__cvta_generic_to_shared(smraw);

    const int tid  = threadIdx.x;
    const int wid  = tid >> 5;
    const int lane = tid & 31;

    // parity CTAs for the same rows adjacent in blockIdx.y -> co-resident,
    // complementary half-sector output writes merge in L2
    const int q    = (int)blockIdx.y & 1;
    const int row0 = ((int)blockIdx.y >> 1) * MT;
    const int n0   = (int)blockIdx.x * NT;

    const int wm = (wid >> 2) * 64;
    const int wn = (wid & 3) * 32;
    const int grp = lane >> 3;
    const int lr  = lane & 7;

    u32 a_rowt[4], a_xor[4];
#pragma unroll
    for (int i = 0; i < 4; ++i) {
        int row = wm + i * 16 + (grp & 1) * 8 + lr;
        a_rowt[i] = (u32)(row * 128);
        a_xor[i]  = (u32)((row & 7) << 4);
    }
    const u32 a_sub16 = (u32)((grp >> 1) * 16);
    u32 b_rowt[2], b_xor[2];
#pragma unroll
    for (int j = 0; j < 2; ++j) {
        int n = wn + j * 16 + (grp >> 1) * 8 + lr;
        b_rowt[j] = (u32)(n * 128);
        b_xor[j]  = (u32)((n & 7) << 4);
    }
    const u32 b_sub16 = (u32)((grp & 1) * 16);

    float acc[4][4][4];
#pragma unroll
    for (int i = 0; i < 4; ++i)
#pragma unroll
        for (int t = 0; t < 4; ++t)
#pragma unroll
            for (int c2 = 0; c2 < 4; ++c2) acc[i][t][c2] = 0.0f;

    stage_chunk(0, sm, row0, n0, q, tid);
    asm volatile("cp.async.commit_group;" ::: "memory");

#pragma unroll 1
    for (int c = 0; c < NCHK; ++c) {
        u32 cur = sm + (u32)(c & 1) * BUFSZ;
        if (c + 1 < NCHK) {
            stage_chunk(c + 1, sm + (u32)((c + 1) & 1) * BUFSZ, row0, n0, q, tid);
            asm volatile("cp.async.commit_group;" ::: "memory");
            asm volatile("cp.async.wait_group 1;" ::: "memory");
        } else {
            asm volatile("cp.async.wait_group 0;" ::: "memory");
        }
        __syncthreads();

        u32 sA = cur, sB = cur + TILEB;
#pragma unroll
        for (int ks = 0; ks < 4; ++ks) {
            const u32 ks32 = (u32)(ks * 32);
            u32 a[4][4];
#pragma unroll
            for (int i = 0; i < 4; ++i)
                ldm4(sA + a_rowt[i] + ((ks32 + a_sub16) ^ a_xor[i]),
                     a[i][0], a[i][1], a[i][2], a[i][3]);
            u32 b[4][2];
#pragma unroll
            for (int j = 0; j < 2; ++j) {
                u32 r0, r1, r2, r3;
                ldm4(sB + b_rowt[j] + ((ks32 + b_sub16) ^ b_xor[j]), r0, r1, r2, r3);
                b[2 * j][0] = r0;     b[2 * j][1] = r1;
                b[2 * j + 1][0] = r2; b[2 * j + 1][1] = r3;
            }
#pragma unroll
            for (int i = 0; i < 4; ++i)
#pragma unroll
                for (int t = 0; t < 4; ++t)
                    mma16816(acc[i][t], a[i], b[t]);
        }
        __syncthreads();
    }

    // epilogue: out[row][2*col'+q] = acc + h0 * A_q[row][col']  (exact diagonal)
    const float h0 = __ldg(&filt[735]);
    const u32* A2 = (const u32*)(q ? g_Ao : g_Ae);
    const int gid = lane >> 2;
    const int tc  = (lane & 3) * 2;
#pragma unroll
    for (int i = 0; i < 4; ++i) {
        int row = row0 + wm + i * 16 + gid;
        if (row >= nrows) continue;
        float* o0 = out + (size_t)row * DET + q;
        float* o1 = o0 + (size_t)8 * DET;
        const u32* a0 = A2 + (size_t)row * (KP / 2);
        const u32* a1 = a0 + (size_t)8 * (KP / 2);
        bool r8ok = (row + 8) < nrows;
#pragma unroll
        for (int t = 0; t < 4; ++t) {
            int col = n0 + wn + t * 8 + tc;          // even; pair idx col/2
            if (col < HDET) {
                float2 d0 = hf2f(a0[col >> 1]);
                o0[2 * col]     = acc[i][t][0] + h0 * d0.x;
                o0[2 * col + 2] = acc[i][t][1] + h0 * d0.y;
                if (r8ok) {
                    float2 d1 = hf2f(a1[col >> 1]);
                    o1[2 * col]     = acc[i][t][2] + h0 * d1.x;
                    o1[2 * col + 2] = acc[i][t][3] + h0 * d1.y;
                }
            }
        }
    }
}

extern "C" void kernel_launch(void* const* d_in, const int* in_sizes, int n_in,
                              void* d_out, int out_size) {
    const float* sino  = (const float*)d_in[0];
    const float* filt  = (const float*)d_in[1];
    const int*   scale = (const int*)d_in[2];
    float* out = (float*)d_out;

    int nrows = in_sizes[0] / DET;              // 18432

    static int inited = 0;
    if (!inited) {
        cudaFuncSetAttribute(gemm_kernel,
                             cudaFuncAttributeMaxDynamicSharedMemorySize, SMEM_DYN);
        inited = 1;
    }

    prep_B<<<2 * KP, 192>>>(filt);
    prep_A<<<nrows, 192>>>(sino, scale, nrows);
    dim3 grid(KP / NT, 2 * MT_HALF);            // (3, 288)
    gemm_kernel<<<grid, 256, SMEM_DYN>>>(out, filt, nrows);
}

// round 12
// speedup vs baseline: 7.1844x; 1.0084x over previous
#include <cuda_runtime.h>
#include <cuda_fp16.h>
#include <cstdint>

#define DET      736
#define HDET     368
#define KP       384                      // padded per-parity K / N
#define MAXR     18432
#define MT       128
#define NT       128
#define KCH      64
#define NCHK     6                        // 64-K chunks (384/64)
#define TILEB    16384                    // 128 rows * 128 B
#define BUFSZ    (2 * TILEB)              // A + B per stage = 32 KB
#define NSTAGE   3
#define SMEM_DYN (NSTAGE * BUFSZ)         // 96 KB triple-buffered
#define MT_HALF  144                      // m-tiles per parity (18432/128)

typedef uint32_t u32;

// parity-split weighted sinogram, single fp16 plane
__device__ __half g_Ae[(size_t)MAXR * KP];
__device__ __half g_Ao[(size_t)MAXR * KP];
// two parity Toeplitz matrices, single fp16 plane: [q][n'][k']
__device__ __half g_Bh[2 * KP * KP];

__device__ __forceinline__ void cpa16(u32 s, const void* g) {
    asm volatile("cp.async.cg.shared.global [%0], [%1], 16;" :: "r"(s), "l"(g));
}
__device__ __forceinline__ void ldm4(u32 a, u32& r0, u32& r1, u32& r2, u32& r3) {
    asm volatile("ldmatrix.sync.aligned.m8n8.x4.shared.b16 {%0,%1,%2,%3}, [%4];"
                 : "=r"(r0), "=r"(r1), "=r"(r2), "=r"(r3) : "r"(a));
}
__device__ __forceinline__ void mma16816(float* c, const u32* a, const u32* b) {
    asm volatile(
        "mma.sync.aligned.m16n8k16.row.col.f32.f16.f16.f32 "
        "{%0,%1,%2,%3}, {%4,%5,%6,%7}, {%8,%9}, {%0,%1,%2,%3};"
        : "+f"(c[0]), "+f"(c[1]), "+f"(c[2]), "+f"(c[3])
        : "r"(a[0]), "r"(a[1]), "r"(a[2]), "r"(a[3]), "r"(b[0]), "r"(b[1]));
}
__device__ __forceinline__ u32 pkhf2(float a, float b) {
    u32 r;
    asm("cvt.rn.f16x2.f32 %0, %1, %2;" : "=r"(r) : "f"(b), "f"(a));
    return r;
}
__device__ __forceinline__ float2 hf2f(u32 h) {
    __half2 v = *(__half2*)&h;
    return make_float2(__half2float(v.x), __half2float(v.y));
}

// ----------------- merged prep kernel -----------------
// blocks [0, 2*KP): Toeplitz B planes; blocks [2*KP, 2*KP+nrows): A rows.
// C0[n'][k'] = filt[736 + 2(k'-n')], C1[n'][k'] = filt[734 + 2(k'-n')]
__global__ void __launch_bounds__(192)
prep_all(const float* __restrict__ filt, const float* __restrict__ x,
         const int* __restrict__ scale_p, int nrows) {
    int b = blockIdx.x;
    int tid = threadIdx.x;
    if (b < 2 * KP) {
        int q  = (b >= KP);
        int np = b - q * KP;
        size_t o = ((size_t)q * KP + np) * KP;
#pragma unroll
        for (int i = 0; i < 2; ++i) {
            int kp = tid + i * 192;
            float v = 0.0f;
            if (np < HDET && kp < HDET) {
                int idx = (q ? 734 : 736) + 2 * (kp - np);
                v = filt[idx];
            }
            g_Bh[o + kp] = __float2half(v);
        }
        return;
    }
    int row = b - 2 * KP;
    if (row >= nrows || row >= MAXR) return;
    int s_i = *scale_p;
    float scale = (s_i >= 1 && s_i <= 1024) ? (float)s_i : __int_as_float(s_i);
    const float kk = scale * 1.0e-3f;
    const float4* xr4 = (const float4*)(x + (size_t)row * DET);
    size_t o2 = (size_t)row * (KP / 2);
    u32* Ae2 = (u32*)g_Ae + o2;
    u32* Ao2 = (u32*)g_Ao + o2;

    int p = tid;                           // covers detectors 4p..4p+3
    float4 v;
    if (2 * p < HDET) v = xr4[p];
    else v = make_float4(0.f, 0.f, 0.f, 0.f);
    float base = (float)(4 * p) - 367.5f;
    float we0 = v.x * (0.05f * __cosf(base * kk));
    float wo0 = v.y * (0.05f * __cosf((base + 1.0f) * kk));
    float we1 = v.z * (0.05f * __cosf((base + 2.0f) * kk));
    float wo1 = v.w * (0.05f * __cosf((base + 3.0f) * kk));

    Ae2[p] = pkhf2(we0, we1);
    Ao2[p] = pkhf2(wo0, wo1);
}

// ----------------- GEMM kernel -----------------

// stage chunk kc: A(16KB) + B(16KB)
__device__ __forceinline__ void stage_chunk(int kc, u32 sbuf, int row0, int n0,
                                            int q, int tid) {
    int k0 = kc * KCH;
    const __half* Abase = ((q == 0) ? g_Ao : g_Ae) + (size_t)row0 * KP + k0;
    const __half* Bbase = g_Bh + (size_t)q * KP * KP + (size_t)n0 * KP + k0;
#pragma unroll
    for (int i = 0; i < 4; ++i) {
        int u = tid + i * 256;
        int r = u >> 3, w = u & 7;
        u32 off = (u32)(r * 128 + w * 16);
        u32 sw  = off ^ ((off >> 3) & 0x70);
        const size_t go = (size_t)r * KP + w * 8;
        cpa16(sbuf + sw,         Abase + go);
        cpa16(sbuf + TILEB + sw, Bbase + go);
    }
}

__global__ void __launch_bounds__(256, 2)
gemm_kernel(float* __restrict__ out, const float* __restrict__ filt, int nrows) {
    extern __shared__ char smraw[];
    u32 sm = (u32)__cvta_generic_to_shared(smraw);

    const int tid  = threadIdx.x;
    const int wid  = tid >> 5;
    const int lane = tid & 31;

    // parity CTAs for the same rows adjacent in blockIdx.y -> co-resident,
    // complementary half-sector output writes merge in L2
    const int q    = (int)blockIdx.y & 1;
    const int row0 = ((int)blockIdx.y >> 1) * MT;
    const int n0   = (int)blockIdx.x * NT;

    const int wm = (wid >> 2) * 64;
    const int wn = (wid & 3) * 32;
    const int grp = lane >> 3;
    const int lr  = lane & 7;

    u32 a_rowt[4], a_xor[4];
#pragma unroll
    for (int i = 0; i < 4; ++i) {
        int row = wm + i * 16 + (grp & 1) * 8 + lr;
        a_rowt[i] = (u32)(row * 128);
        a_xor[i]  = (u32)((row & 7) << 4);
    }
    const u32 a_sub16 = (u32)((grp >> 1) * 16);
    u32 b_rowt[2], b_xor[2];
#pragma unroll
    for (int j = 0; j < 2; ++j) {
        int n = wn + j * 16 + (grp >> 1) * 8 + lr;
        b_rowt[j] = (u32)(n * 128);
        b_xor[j]  = (u32)((n & 7) << 4);
    }
    const u32 b_sub16 = (u32)((grp & 1) * 16);

    float acc[4][4][4];
#pragma unroll
    for (int i = 0; i < 4; ++i)
#pragma unroll
        for (int t = 0; t < 4; ++t)
#pragma unroll
            for (int c2 = 0; c2 < 4; ++c2) acc[i][t][c2] = 0.0f;

    // 3-stage pipeline: prologue preloads chunks 0 and 1
    stage_chunk(0, sm + 0 * BUFSZ, row0, n0, q, tid);
    asm volatile("cp.async.commit_group;" ::: "memory");
    stage_chunk(1, sm + 1 * BUFSZ, row0, n0, q, tid);
    asm volatile("cp.async.commit_group;" ::: "memory");

#pragma unroll 1
    for (int c = 0; c < NCHK; ++c) {
        asm volatile("cp.async.wait_group 1;" ::: "memory");  // chunk c arrived
        __syncthreads();   // all warps done with buf((c-1)%3) from last iter
        if (c + 2 < NCHK) {
            int nb = (c + 2) % NSTAGE;
            stage_chunk(c + 2, sm + (u32)nb * BUFSZ, row0, n0, q, tid);
        }
        asm volatile("cp.async.commit_group;" ::: "memory");  // keep group count

        u32 cur = sm + (u32)(c % NSTAGE) * BUFSZ;
        u32 sA = cur, sB = cur + TILEB;
#pragma unroll
        for (int ks = 0; ks < 4; ++ks) {
            const u32 ks32 = (u32)(ks * 32);
            u32 a[4][4];
#pragma unroll
            for (int i = 0; i < 4; ++i)
                ldm4(sA + a_rowt[i] + ((ks32 + a_sub16) ^ a_xor[i]),
                     a[i][0], a[i][1], a[i][2], a[i][3]);
            u32 b[4][2];
#pragma unroll
            for (int j = 0; j < 2; ++j) {
                u32 r0, r1, r2, r3;
                ldm4(sB + b_rowt[j] + ((ks32 + b_sub16) ^ b_xor[j]), r0, r1, r2, r3);
                b[2 * j][0] = r0;     b[2 * j][1] = r1;
                b[2 * j + 1][0] = r2; b[2 * j + 1][1] = r3;
            }
#pragma unroll
            for (int i = 0; i < 4; ++i)
#pragma unroll
                for (int t = 0; t < 4; ++t)
                    mma16816(acc[i][t], a[i], b[t]);
        }
    }

    // epilogue: out[row][2*col'+q] = acc + h0 * A_q[row][col']  (exact diagonal)
    const float h0 = __ldg(&filt[735]);
    const u32* A2 = (const u32*)(q ? g_Ao : g_Ae);
    const int gid = lane >> 2;
    const int tc  = (lane & 3) * 2;
#pragma unroll
    for (int i = 0; i < 4; ++i) {
        int row = row0 + wm + i * 16 + gid;
        if (row >= nrows) continue;
        float* o0 = out + (size_t)row * DET + q;
        float* o1 = o0 + (size_t)8 * DET;
        const u32* a0 = A2 + (size_t)row * (KP / 2);
        const u32* a1 = a0 + (size_t)8 * (KP / 2);
        bool r8ok = (row + 8) < nrows;
#pragma unroll
        for (int t = 0; t < 4; ++t) {
            int col = n0 + wn + t * 8 + tc;          // even; pair idx col/2
            if (col < HDET) {
                float2 d0 = hf2f(a0[col >> 1]);
                o0[2 * col]     = acc[i][t][0] + h0 * d0.x;
                o0[2 * col + 2] = acc[i][t][1] + h0 * d0.y;
                if (r8ok) {
                    float2 d1 = hf2f(a1[col >> 1]);
                    o1[2 * col]     = acc[i][t][2] + h0 * d1.x;
                    o1[2 * col + 2] = acc[i][t][3] + h0 * d1.y;
                }
            }
        }
    }
}

extern "C" void kernel_launch(void* const* d_in, const int* in_sizes, int n_in,
                              void* d_out, int out_size) {
    const float* sino  = (const float*)d_in[0];
    const float* filt  = (const float*)d_in[1];
    const int*   scale = (const int*)d_in[2];
    float* out = (float*)d_out;

    int nrows = in_sizes[0] / DET;              // 18432

    static int inited = 0;
    if (!inited) {
        cudaFuncSetAttribute(gemm_kernel,
                             cudaFuncAttributeMaxDynamicSharedMemorySize, SMEM_DYN);
        inited = 1;
    }

    prep_all<<<2 * KP + nrows, 192>>>(filt, sino, scale, nrows);
    dim3 grid(KP / NT, 2 * MT_HALF);            // (3, 288)
    gemm_kernel<<<grid, 256, SMEM_DYN>>>(out, filt, nrows);
}